// round 3
// baseline (speedup 1.0000x reference)
#include <cuda_runtime.h>
#include <cstdint>

// Problem constants
#define Bsz 4
#define Nn  1024
#define Ff  256
#define NW  32          // 1024 bits -> 32 u32 words per row
#define FULL 0xFFFFFFFFu

// Output layout (float32, tuple flattened): x_p [B,N,F], pos_p [B,N,3], a [B,N,N], mask [B,N]
#define OFF_XP   0
#define OFF_POS  (Bsz*Nn*Ff)                 // 1048576
#define OFF_A    (OFF_POS + Bsz*Nn*3)        // 1060864
#define OFF_MASK (OFF_A + Bsz*Nn*Nn)         // 5255168

// Scratch (device globals; no allocations allowed)
__device__ uint32_t g_bits[Bsz*Nn*NW];   // A != 0 bitmask rows
__device__ uint32_t g_inc [Bsz*Nn*NW];   // adj2 != 0 bitmask rows
__device__ int      g_perm[Bsz*Nn];
__device__ int      g_K[Bsz];

// ---------------------------------------------------------------------------
// Zero the x_p / pos_p / a regions (mask region is fully written by k_select)
__global__ void k_zero(float4* __restrict__ p, int n4) {
    int i = blockIdx.x * blockDim.x + threadIdx.x;
    int stride = gridDim.x * blockDim.x;
    float4 z = make_float4(0.f, 0.f, 0.f, 0.f);
    for (; i < n4; i += stride) p[i] = z;
}

// ---------------------------------------------------------------------------
// Build adjacency bitmasks: one warp per 32-bit word. Coalesced 16MB read.
__global__ void k_bits(const float* __restrict__ adj) {
    int wid  = (blockIdx.x * blockDim.x + threadIdx.x) >> 5;  // [0, B*N*NW)
    int lane = threadIdx.x & 31;
    int w    = wid & 31;
    int row  = wid >> 5;           // b*N + i
    float v  = adj[(size_t)row * Nn + w * 32 + lane];
    uint32_t bits = __ballot_sync(FULL, v != 0.0f);
    if (lane == 0) g_bits[row * NW + w] = bits;
}

// ---------------------------------------------------------------------------
// inc_row(i) = (A^2 + A)[i] != 0 = union of neighbor rows | own row.
// One warp per node row; lane owns one word. ~deg(i) coalesced 128B row loads.
__global__ void k_inc() {
    int wid  = (blockIdx.x * blockDim.x + threadIdx.x) >> 5;
    int lane = threadIdx.x & 31;
    if (wid >= Bsz * Nn) return;
    int b = wid >> 10;
    int rowbase = wid * NW;
    uint32_t myw = g_bits[rowbase + lane];
    uint32_t acc = myw;
    for (int w = 0; w < NW; ++w) {
        uint32_t mw = __shfl_sync(FULL, myw, w);
        while (mw) {
            int j = __ffs(mw) - 1; mw &= mw - 1;
            int k = w * 32 + j;
            acc |= g_bits[(b * Nn + k) * NW + lane];
        }
    }
    g_inc[rowbase + lane] = acc;
}

// ---------------------------------------------------------------------------
// Sequential greedy frontier selection (K-MIS stride 2), one warp per batch.
// Exactly mirrors the JAX while_loop semantics (incl. frontier-restart rule
// and argmin first-index tie-break). Also builds perm (stable top_k of 0/1)
// and writes the mask output.
__global__ void k_select(const float* __restrict__ order, float* __restrict__ out_mask) {
    int b = blockIdx.x;
    int lane = threadIdx.x;
    const float* ob = order + b * Nn;

    // cache this lane's 32 order values in registers (nodes lane*32 .. +31)
    float ord[32];
#pragma unroll
    for (int j = 0; j < 32; ++j) ord[j] = ob[lane * 32 + j];

    uint32_t av = FULL, sel = 0u, fr = 0u;

    // idx0 = argmin over all nodes
    float bv = 3.0e38f; int bi = 0x7fffffff;
#pragma unroll
    for (int j = 0; j < 32; ++j) {
        float v = ord[j];
        if (v < bv) { bv = v; bi = lane * 32 + j; }
    }
    for (int off = 16; off; off >>= 1) {
        float ov = __shfl_down_sync(FULL, bv, off);
        int   oi = __shfl_down_sync(FULL, bi, off);
        if (ov < bv || (ov == bv && oi < bi)) { bv = ov; bi = oi; }
    }
    bi = __shfl_sync(FULL, bi, 0);
    int idx = bi;

    fr = (lane == (idx >> 5)) ? (1u << (idx & 31)) : 0u;
    bool fr_any = true;

    while (__ballot_sync(FULL, av != 0u)) {
        uint32_t cur = (lane == (idx >> 5)) ? (1u << (idx & 31)) : 0u;
        sel |= cur;
        uint32_t exc = g_bits[(b * Nn + idx) * NW + lane] | cur;  // adj1 row != 0
        uint32_t inc = g_inc [(b * Nn + idx) * NW + lane];        // adj2 row != 0
        av &= ~exc;                       // cur subset of exc
        uint32_t frn = fr_any ? (fr | inc) : FULL;  // restart if old frontier empty
        fr = frn & av;

        // argmin(order) over frontier
        bv = 3.0e38f; bi = 0x7fffffff;
#pragma unroll
        for (int j = 0; j < 32; ++j) {
            if ((fr >> j) & 1u) {
                float v = ord[j];
                if (v < bv) { bv = v; bi = lane * 32 + j; }
            }
        }
        for (int off = 16; off; off >>= 1) {
            float ov = __shfl_down_sync(FULL, bv, off);
            int   oi = __shfl_down_sync(FULL, bi, off);
            if (ov < bv || (ov == bv && oi < bi)) { bv = ov; bi = oi; }
        }
        bi = __shfl_sync(FULL, bi, 0);

        fr_any = (__ballot_sync(FULL, fr != 0u) != 0u);
        if (fr_any) idx = bi;
    }

    // Stable top_k of 0/1 floats == selected indices ascending, then unselected.
    int cnt = __popc(sel);
    int incl = cnt;
    for (int off = 1; off < 32; off <<= 1) {
        int v = __shfl_up_sync(FULL, incl, off);
        if (lane >= off) incl += v;
    }
    int excl = incl - cnt;
    int K = __shfl_sync(FULL, incl, 31);

    uint32_t s = sel; int r = 0;
    while (s) { int j = __ffs(s) - 1; s &= s - 1; g_perm[b * Nn + excl + r] = lane * 32 + j; ++r; }
    int excl_u = lane * 32 - excl;
    s = ~sel; r = 0;
    while (s) { int j = __ffs(s) - 1; s &= s - 1; g_perm[b * Nn + K + excl_u + r] = lane * 32 + j; ++r; }

    if (lane == 0) g_K[b] = K;
    for (int t = lane; t < Nn; t += 32)
        out_mask[b * Nn + t] = (t < K) ? 1.0f : 0.0f;
}

// ---------------------------------------------------------------------------
// x_p[b,k,f] = sum_{n in N(j)} x[b,n,f] + x[b,j,f], j = perm[b,k], k < K.
// One block (256 threads = F columns) per (b,k). Non-selected rows stay zero.
__global__ void k_xp(const float* __restrict__ x, float* __restrict__ out_xp) {
    int b = blockIdx.y, k = blockIdx.x;
    if (k >= g_K[b]) return;
    int j = g_perm[b * Nn + k];
    __shared__ uint32_t sh[NW];
    if (threadIdx.x < NW) sh[threadIdx.x] = g_bits[(b * Nn + j) * NW + threadIdx.x];
    __syncthreads();
    int f = threadIdx.x;
    const float* xb = x + (size_t)b * Nn * Ff;
    float acc = xb[(size_t)j * Ff + f];
    for (int w = 0; w < NW; ++w) {
        uint32_t m = sh[w];
        while (m) {
            int n = w * 32 + __ffs(m) - 1; m &= m - 1;
            acc += xb[(size_t)n * Ff + f];
        }
    }
    out_xp[((size_t)(b * Nn) + k) * Ff + f] = acc;
}

// ---------------------------------------------------------------------------
// pos_p[b,k,:] = (sum_{n in N(j)} pos[n] + pos[j]) / (deg(j)+1). Warp per (b,k).
__global__ void k_pos(const float* __restrict__ pos, float* __restrict__ out_pos) {
    int wid  = (blockIdx.x * blockDim.x + threadIdx.x) >> 5;
    int lane = threadIdx.x & 31;
    if (wid >= Bsz * Nn) return;
    int b = wid >> 10, k = wid & (Nn - 1);
    if (k >= g_K[b]) return;
    int j = g_perm[b * Nn + k];
    uint32_t m = g_bits[(b * Nn + j) * NW + lane];
    const float* pb = pos + (size_t)b * Nn * 3;
    float sx = 0.f, sy = 0.f, sz = 0.f;
    int c = __popc(m);
    while (m) {
        int n = lane * 32 + __ffs(m) - 1; m &= m - 1;
        sx += pb[n * 3 + 0]; sy += pb[n * 3 + 1]; sz += pb[n * 3 + 2];
    }
    for (int off = 16; off; off >>= 1) {
        sx += __shfl_down_sync(FULL, sx, off);
        sy += __shfl_down_sync(FULL, sy, off);
        sz += __shfl_down_sync(FULL, sz, off);
        c  += __shfl_down_sync(FULL, c,  off);
    }
    if (lane == 0) {
        float deg = (float)(c + 1);
        out_pos[(b * Nn + k) * 3 + 0] = (sx + pb[j * 3 + 0]) / deg;
        out_pos[(b * Nn + k) * 3 + 1] = (sy + pb[j * 3 + 1]) / deg;
        out_pos[(b * Nn + k) * 3 + 2] = (sz + pb[j * 3 + 2]) / deg;
    }
}

// ---------------------------------------------------------------------------
// a[b,k1,k2] = popc(bits_{p1} & bits_{p2}) + A[p1,p2]   (k1,k2 < K), else 0.
// One block per (b,k1); bits_{p1} in shared; thread per k2.
__global__ void k_a(const float* __restrict__ adj, float* __restrict__ out_a) {
    int b = blockIdx.y, k1 = blockIdx.x;
    if (k1 >= g_K[b]) return;
    int p1 = g_perm[b * Nn + k1];
    __shared__ uint32_t sh[NW];
    if (threadIdx.x < NW) sh[threadIdx.x] = g_bits[(b * Nn + p1) * NW + threadIdx.x];
    __syncthreads();
    int Kc = g_K[b];
    const float* ab = adj + (size_t)(b * Nn + p1) * Nn;
    for (int k2 = threadIdx.x; k2 < Kc; k2 += blockDim.x) {
        int p2 = g_perm[b * Nn + k2];
        int c = 0;
#pragma unroll
        for (int w = 0; w < NW; ++w)
            c += __popc(sh[w] & g_bits[(b * Nn + p2) * NW + w]);
        out_a[((size_t)(b * Nn) + k1) * Nn + k2] = (float)c + ab[p2];
    }
}

// ---------------------------------------------------------------------------
extern "C" void kernel_launch(void* const* d_in, const int* in_sizes, int n_in,
                              void* d_out, int out_size) {
    const float* x     = (const float*)d_in[0];
    const float* adj   = (const float*)d_in[1];
    const float* pos   = (const float*)d_in[2];
    const float* order = (const float*)d_in[3];
    float* out = (float*)d_out;

    // zero x_p / pos_p / a regions (OFF_MASK floats, 16B aligned & divisible by 4)
    k_zero<<<2048, 256>>>((float4*)out, OFF_MASK / 4);
    // adjacency bitmasks: B*N*NW warps
    k_bits<<<(Bsz * Nn * NW * 32) / 256, 256>>>(adj);
    // 2-hop reach bitmasks: B*N warps
    k_inc<<<(Bsz * Nn * 32) / 256, 256>>>();
    // sequential selection, perm, mask
    k_select<<<Bsz, 32>>>(order, out + OFF_MASK);
    // pooled outputs
    k_xp<<<dim3(Nn, Bsz), 256>>>(x, out + OFF_XP);
    k_pos<<<(Bsz * Nn * 32) / 256, 256>>>(pos, out + OFF_POS);
    k_a<<<dim3(Nn, Bsz), 256>>>(adj, out + OFF_A);
}